// round 13
// baseline (speedup 1.0000x reference)
#include <cuda_runtime.h>
#include <cuda_bf16.h>
#include <math.h>
#include <stdint.h>

#define N 4096
#define D 768
#define TEMP_INV 20.0f
#define EPSN 1e-8f
#define SHIFT 4.0f
#define LOG2E 1.44269504089f

#define BK 64
#define NCH (D / BK)          // 12 k-chunks
#define STAGE_BYTES 32768     // 16KB A + 16KB B
#define SMEM_DYN (3 * STAGE_BYTES)   // 96 KB -> 2 CTA/SM

// ---------------------------------------------------------------------------
// Scratch (allocation-free: device globals)
// ---------------------------------------------------------------------------
__device__ __nv_bfloat16 g_a[(size_t)N * D];
__device__ __nv_bfloat16 g_b[(size_t)N * D];
__device__ float g_partial2[(size_t)N * 128];  // per (row, colblock*4 + colwarp)
__device__ float g_diag[N];                    // exact fp32 diagonal logits
__device__ float g_rowloss[N];
__device__ int   g_done;

// ---------------------------------------------------------------------------
__device__ __forceinline__ uint32_t smem_u32(const void* p) {
    uint32_t a;
    asm("{ .reg .u64 t; cvta.to.shared.u64 t, %1; cvt.u32.u64 %0, t; }" : "=r"(a) : "l"(p));
    return a;
}

#define CP_ASYNC16(dst, src) \
    asm volatile("cp.async.cg.shared.global [%0], [%1], 16;" :: "r"(dst), "l"(src) : "memory")
#define CP_COMMIT() asm volatile("cp.async.commit_group;" ::: "memory")
#define CP_WAIT(n)  asm volatile("cp.async.wait_group %0;" :: "n"(n) : "memory")

__device__ __forceinline__ void ldmx4(uint32_t* r, uint32_t addr) {
    asm volatile("ldmatrix.sync.aligned.m8n8.x4.shared.b16 {%0,%1,%2,%3}, [%4];"
                 : "=r"(r[0]), "=r"(r[1]), "=r"(r[2]), "=r"(r[3]) : "r"(addr));
}

__device__ __forceinline__ void mma_bf16(float* c, const uint32_t* a, const uint32_t* b) {
    asm volatile(
        "mma.sync.aligned.m16n8k16.row.col.f32.bf16.bf16.f32 "
        "{%0,%1,%2,%3}, {%4,%5,%6,%7}, {%8,%9}, {%0,%1,%2,%3};"
        : "+f"(c[0]), "+f"(c[1]), "+f"(c[2]), "+f"(c[3])
        : "r"(a[0]), "r"(a[1]), "r"(a[2]), "r"(a[3]), "r"(b[0]), "r"(b[1]));
}

__device__ __forceinline__ uint32_t pack_f16x2(float x, float y) {
    uint32_t r;
    asm("cvt.rn.f16x2.f32 %0, %1, %2;" : "=r"(r) : "f"(y), "f"(x));
    return r;
}
__device__ __forceinline__ uint32_t ex2_f16x2(uint32_t h) {
    uint32_t r;
    asm("ex2.approx.f16x2 %0, %1;" : "=r"(r) : "r"(h));
    return r;
}
__device__ __forceinline__ uint32_t hadd2(uint32_t a, uint32_t b) {
    uint32_t r;
    asm("add.f16x2 %0, %1, %2;" : "=r"(r) : "r"(a), "r"(b));
    return r;
}
__device__ __forceinline__ float h2_sum_f32(uint32_t h) {
    __half2 v = *reinterpret_cast<__half2*>(&h);
    return __half2float(__low2half(v)) + __half2float(__high2half(v));
}
__device__ __forceinline__ uint32_t pack_bf162_u32(float x, float y) {
    __nv_bfloat162 b = __floats2bfloat162_rn(x, y);
    return *reinterpret_cast<uint32_t*>(&b);
}

// ---------------------------------------------------------------------------
// Kernel 1: warp-per-row L2-normalize BOTH matrices, bf16 out (8B stores),
// exact fp32 diagonal logit. Resets g_done. grid = N/8 = 512 x 256 threads.
// ---------------------------------------------------------------------------
__global__ __launch_bounds__(256)
void k_norm_cvt(const float* __restrict__ f1, const float* __restrict__ f2) {
    if (blockIdx.x == 0 && threadIdx.x == 0) g_done = 0;

    const int wid = threadIdx.x >> 5;
    const int lane = threadIdx.x & 31;
    const int row = blockIdx.x * 8 + wid;

    const float4* p1 = (const float4*)(f1 + (size_t)row * D);
    const float4* p2 = (const float4*)(f2 + (size_t)row * D);
    float4 v1[6], v2[6];
    float ss1 = 0.0f, ss2 = 0.0f, s12 = 0.0f;
    #pragma unroll
    for (int i = 0; i < 6; i++) {
        v1[i] = p1[lane + i * 32];
        v2[i] = p2[lane + i * 32];
        ss1 += v1[i].x * v1[i].x + v1[i].y * v1[i].y + v1[i].z * v1[i].z + v1[i].w * v1[i].w;
        ss2 += v2[i].x * v2[i].x + v2[i].y * v2[i].y + v2[i].z * v2[i].z + v2[i].w * v2[i].w;
        s12 += v1[i].x * v2[i].x + v1[i].y * v2[i].y + v1[i].z * v2[i].z + v1[i].w * v2[i].w;
    }
    #pragma unroll
    for (int off = 16; off > 0; off >>= 1) {
        ss1 += __shfl_xor_sync(0xFFFFFFFFu, ss1, off);
        ss2 += __shfl_xor_sync(0xFFFFFFFFu, ss2, off);
        s12 += __shfl_xor_sync(0xFFFFFFFFu, s12, off);
    }
    const float inv1 = 1.0f / fmaxf(sqrtf(ss1), EPSN);
    const float inv2 = 1.0f / fmaxf(sqrtf(ss2), EPSN);
    if (lane == 0) g_diag[row] = TEMP_INV * s12 * inv1 * inv2;

    uint2* q1 = (uint2*)(g_a + (size_t)row * D);
    uint2* q2 = (uint2*)(g_b + (size_t)row * D);
    #pragma unroll
    for (int i = 0; i < 6; i++) {
        const int idx = lane + i * 32;
        q1[idx] = make_uint2(pack_bf162_u32(v1[i].x * inv1, v1[i].y * inv1),
                             pack_bf162_u32(v1[i].z * inv1, v1[i].w * inv1));
        q2[idx] = make_uint2(pack_bf162_u32(v2[i].x * inv2, v2[i].y * inv2),
                             pack_bf162_u32(v2[i].z * inv2, v2[i].w * inv2));
    }
}

// ---------------------------------------------------------------------------
// Kernel 2: bf16 mma.sync GEMM (proven 72.2us mainloop), 128x128 CTA tile,
// 256 threads, 8 warps (2x4), warp tile 64x32, BK=64, 3-stage cp.async,
// XOR-8 swizzle, f16x2-exp2 fused epilogue with DIRECT gmem partial stores
// (no smem transpose, no post-mainloop barriers).
// ---------------------------------------------------------------------------
__global__ __launch_bounds__(256)
void k_gemm_fused() {
    extern __shared__ char smem[];
    const uint32_t sbase = smem_u32(smem);
    const int tid = threadIdx.x;
    const int wid = tid >> 5;
    const int lane = tid & 31;
    const int bx = blockIdx.x, by = blockIdx.y;
    const int bi = by * 128, bj = bx * 128;

    const int wy = wid >> 2;
    const int wx = wid & 3;
    const int m0 = wy * 64;
    const int n0 = wx * 32;

    auto load_chunk = [&](int c, int s) {
        const int k0 = c * BK;
        const uint32_t st = sbase + s * STAGE_BYTES;
        #pragma unroll
        for (int i = 0; i < 8; i++) {
            const int idx = tid + i * 256;          // 0..2047
            const int isB = idx >> 10;
            const int id2 = idx & 1023;
            const int row = id2 >> 3;               // 0..127
            const int ch  = id2 & 7;                // 16B chunk in 128B row
            const uint32_t soff = (uint32_t)(row * 128 + ((ch ^ (row & 7)) << 4));
            const __nv_bfloat16* src = (isB ? g_b + (size_t)(bj + row) * D
                                            : g_a + (size_t)(bi + row) * D) + k0 + ch * 8;
            CP_ASYNC16(st + isB * 16384 + soff, src);
        }
        CP_COMMIT();
    };

    uint32_t aRB[4], aR7[4];
    #pragma unroll
    for (int mt = 0; mt < 4; mt++) {
        const int r = m0 + mt * 16 + (lane & 15);
        aRB[mt] = (uint32_t)(r * 128);
        aR7[mt] = (uint32_t)(r & 7);
    }
    uint32_t bRB[2], bR7[2];
    #pragma unroll
    for (int p = 0; p < 2; p++) {
        const int r = n0 + p * 16 + ((lane >> 4) << 3) + (lane & 7);
        bRB[p] = (uint32_t)(r * 128);
        bR7[p] = (uint32_t)(r & 7);
    }
    const uint32_t chA = (uint32_t)(lane >> 4);
    const uint32_t chB = (uint32_t)((lane >> 3) & 1);

    float acc[4][4][4];
    #pragma unroll
    for (int mt = 0; mt < 4; mt++)
        #pragma unroll
        for (int nt = 0; nt < 4; nt++)
            #pragma unroll
            for (int r = 0; r < 4; r++) acc[mt][nt][r] = 0.0f;

    load_chunk(0, 0);
    load_chunk(1, 1);

    for (int c = 0; c < NCH; c++) {
        CP_WAIT(1);
        __syncthreads();
        if (c + 2 < NCH) {
            load_chunk(c + 2, (c + 2) % 3);
        } else {
            CP_COMMIT();
        }

        const uint32_t sA = sbase + (c % 3) * STAGE_BYTES;
        const uint32_t sB = sA + 16384;

        #pragma unroll
        for (int ks = 0; ks < 4; ks++) {
            uint32_t a[4][4];
            #pragma unroll
            for (int mt = 0; mt < 4; mt++) {
                const uint32_t ch = 2 * ks + chA;
                ldmx4(a[mt], sA + aRB[mt] + ((ch ^ aR7[mt]) << 4));
            }
            uint32_t b[4][2];
            #pragma unroll
            for (int p = 0; p < 2; p++) {
                uint32_t t[4];
                const uint32_t ch = 2 * ks + chB;
                ldmx4(t, sB + bRB[p] + ((ch ^ bR7[p]) << 4));
                b[2 * p][0] = t[0]; b[2 * p][1] = t[1];
                b[2 * p + 1][0] = t[2]; b[2 * p + 1][1] = t[3];
            }
            #pragma unroll
            for (int mt = 0; mt < 4; mt++)
                #pragma unroll
                for (int nt = 0; nt < 4; nt++)
                    mma_bf16(acc[mt][nt], a[mt], b[nt]);
        }
    }

    // -------- fused epilogue: f16x2 exp2 (shift 4), direct gmem partials ----
    const float S = TEMP_INV * LOG2E;
    const float Bc = -SHIFT * LOG2E;
    const int g = lane >> 2;
    const int tig = lane & 3;

    uint32_t hsum[8];
    #pragma unroll
    for (int h = 0; h < 8; h++) hsum[h] = 0u;

    #pragma unroll
    for (int mt = 0; mt < 4; mt++) {
        #pragma unroll
        for (int nt = 0; nt < 4; nt++) {
            const uint32_t e01 = ex2_f16x2(pack_f16x2(fmaf(acc[mt][nt][0], S, Bc),
                                                      fmaf(acc[mt][nt][1], S, Bc)));
            const uint32_t e23 = ex2_f16x2(pack_f16x2(fmaf(acc[mt][nt][2], S, Bc),
                                                      fmaf(acc[mt][nt][3], S, Bc)));
            hsum[mt * 2 + 0] = hadd2(hsum[mt * 2 + 0], e01);
            hsum[mt * 2 + 1] = hadd2(hsum[mt * 2 + 1], e23);
        }
    }

    float rowsum[8];
    #pragma unroll
    for (int h = 0; h < 8; h++) {
        rowsum[h] = h2_sum_f32(hsum[h]);
        rowsum[h] += __shfl_xor_sync(0xFFFFFFFFu, rowsum[h], 1);
        rowsum[h] += __shfl_xor_sync(0xFFFFFFFFu, rowsum[h], 2);
    }

    // direct store: one partial per (row, bx*4+wx); no smem, no barriers
    if (tig == 0) {
        #pragma unroll
        for (int h = 0; h < 8; h++) {
            const int row = bi + m0 + (h >> 1) * 16 + (h & 1) * 8 + g;
            g_partial2[(size_t)row * 128 + bx * 4 + wx] = rowsum[h];
        }
    }
}

// ---------------------------------------------------------------------------
// Kernel 3: per-row loss (sum 128 partials) + deterministic mean.
// loss_i = log(sum_j exp(l_ij - 4)) + 4 - l_ii(exact)
// ---------------------------------------------------------------------------
__global__ void k_rowloss_fin(float* __restrict__ out) {
    const int row = blockIdx.x * 128 + threadIdx.x;
    const float4* p = (const float4*)(g_partial2 + (size_t)row * 128);
    float s = 0.0f;
    #pragma unroll
    for (int i = 0; i < 32; i++) {
        float4 v = p[i];
        s += v.x + v.y + v.z + v.w;
    }
    g_rowloss[row] = logf(s) + SHIFT - g_diag[row];

    __threadfence();
    __shared__ bool isLast;
    if (threadIdx.x == 0) {
        isLast = (atomicAdd(&g_done, 1) == 31);
    }
    __syncthreads();
    if (!isLast) return;

    float t = 0.0f;
    const float4* rl = (const float4*)g_rowloss;
    #pragma unroll
    for (int i = 0; i < 8; i++) {
        float4 v = rl[threadIdx.x + i * 128];
        t += v.x + v.y + v.z + v.w;
    }
    __shared__ float sm[128];
    sm[threadIdx.x] = t;
    __syncthreads();
    #pragma unroll
    for (int off = 64; off > 0; off >>= 1) {
        if (threadIdx.x < off) sm[threadIdx.x] += sm[threadIdx.x + off];
        __syncthreads();
    }
    if (threadIdx.x == 0) out[0] = sm[0] / (float)N;
}

// ---------------------------------------------------------------------------
extern "C" void kernel_launch(void* const* d_in, const int* in_sizes, int n_in,
                              void* d_out, int out_size) {
    const float* f1 = (const float*)d_in[0];
    const float* f2 = (const float*)d_in[1];
    float* out = (float*)d_out;

    cudaFuncSetAttribute(k_gemm_fused, cudaFuncAttributeMaxDynamicSharedMemorySize, SMEM_DYN);

    k_norm_cvt<<<N / 8, 256>>>(f1, f2);
    k_gemm_fused<<<dim3(N / 128, N / 128), 256, SMEM_DYN>>>();
    k_rowloss_fin<<<32, 128>>>(out);
}

// round 14
// speedup vs baseline: 1.0565x; 1.0565x over previous
#include <cuda_runtime.h>
#include <cuda_bf16.h>
#include <math.h>
#include <stdint.h>

#define N 4096
#define D 768
#define TEMP_INV 20.0f
#define EPSN 1e-8f
#define SHIFT 4.0f
#define LOG2E 1.44269504089f

#define BK 64
#define NCH (D / BK)          // 12 k-chunks
#define STAGE_BYTES 32768     // 16KB A + 16KB B
#define SMEM_DYN (3 * STAGE_BYTES)   // 96 KB -> 2 CTA/SM

// ---------------------------------------------------------------------------
// Scratch (allocation-free: device globals)
// ---------------------------------------------------------------------------
__device__ __nv_bfloat16 g_a[(size_t)N * D];
__device__ __nv_bfloat16 g_b[(size_t)N * D];
__device__ float g_partial[(size_t)N * 32];
__device__ float g_diag[N];          // exact fp32 diagonal logits
__device__ float g_rowloss[N];
__device__ int   g_done;

// ---------------------------------------------------------------------------
__device__ __forceinline__ uint32_t smem_u32(const void* p) {
    uint32_t a;
    asm("{ .reg .u64 t; cvta.to.shared.u64 t, %1; cvt.u32.u64 %0, t; }" : "=r"(a) : "l"(p));
    return a;
}

#define CP_ASYNC16(dst, src) \
    asm volatile("cp.async.cg.shared.global [%0], [%1], 16;" :: "r"(dst), "l"(src) : "memory")
#define CP_COMMIT() asm volatile("cp.async.commit_group;" ::: "memory")
#define CP_WAIT(n)  asm volatile("cp.async.wait_group %0;" :: "n"(n) : "memory")

__device__ __forceinline__ void ldmx4(uint32_t* r, uint32_t addr) {
    asm volatile("ldmatrix.sync.aligned.m8n8.x4.shared.b16 {%0,%1,%2,%3}, [%4];"
                 : "=r"(r[0]), "=r"(r[1]), "=r"(r[2]), "=r"(r[3]) : "r"(addr));
}

__device__ __forceinline__ void mma_bf16(float* c, const uint32_t* a, const uint32_t* b) {
    asm volatile(
        "mma.sync.aligned.m16n8k16.row.col.f32.bf16.bf16.f32 "
        "{%0,%1,%2,%3}, {%4,%5,%6,%7}, {%8,%9}, {%0,%1,%2,%3};"
        : "+f"(c[0]), "+f"(c[1]), "+f"(c[2]), "+f"(c[3])
        : "r"(a[0]), "r"(a[1]), "r"(a[2]), "r"(a[3]), "r"(b[0]), "r"(b[1]));
}

__device__ __forceinline__ uint32_t pack_f16x2(float x, float y) {
    uint32_t r;
    asm("cvt.rn.f16x2.f32 %0, %1, %2;" : "=r"(r) : "f"(y), "f"(x));
    return r;
}
__device__ __forceinline__ uint32_t ex2_f16x2(uint32_t h) {
    uint32_t r;
    asm("ex2.approx.f16x2 %0, %1;" : "=r"(r) : "r"(h));
    return r;
}
__device__ __forceinline__ uint32_t hadd2(uint32_t a, uint32_t b) {
    uint32_t r;
    asm("add.f16x2 %0, %1, %2;" : "=r"(r) : "r"(a), "r"(b));
    return r;
}
__device__ __forceinline__ float h2_sum_f32(uint32_t h) {
    __half2 v = *reinterpret_cast<__half2*>(&h);
    return __half2float(__low2half(v)) + __half2float(__high2half(v));
}
__device__ __forceinline__ uint32_t pack_bf162_u32(float x, float y) {
    __nv_bfloat162 b = __floats2bfloat162_rn(x, y);
    return *reinterpret_cast<uint32_t*>(&b);
}

// ---------------------------------------------------------------------------
// Kernel 1: warp-per-row L2-normalize BOTH matrices, bf16 out (8B stores),
// exact fp32 diagonal logit. Resets g_done. grid = N/8 = 512 x 256 threads.
// ---------------------------------------------------------------------------
__global__ __launch_bounds__(256)
void k_norm_cvt(const float* __restrict__ f1, const float* __restrict__ f2) {
    if (blockIdx.x == 0 && threadIdx.x == 0) g_done = 0;

    const int wid = threadIdx.x >> 5;
    const int lane = threadIdx.x & 31;
    const int row = blockIdx.x * 8 + wid;

    const float4* p1 = (const float4*)(f1 + (size_t)row * D);
    const float4* p2 = (const float4*)(f2 + (size_t)row * D);
    float4 v1[6], v2[6];
    float ss1 = 0.0f, ss2 = 0.0f, s12 = 0.0f;
    #pragma unroll
    for (int i = 0; i < 6; i++) {
        v1[i] = p1[lane + i * 32];
        v2[i] = p2[lane + i * 32];
        ss1 += v1[i].x * v1[i].x + v1[i].y * v1[i].y + v1[i].z * v1[i].z + v1[i].w * v1[i].w;
        ss2 += v2[i].x * v2[i].x + v2[i].y * v2[i].y + v2[i].z * v2[i].z + v2[i].w * v2[i].w;
        s12 += v1[i].x * v2[i].x + v1[i].y * v2[i].y + v1[i].z * v2[i].z + v1[i].w * v2[i].w;
    }
    #pragma unroll
    for (int off = 16; off > 0; off >>= 1) {
        ss1 += __shfl_xor_sync(0xFFFFFFFFu, ss1, off);
        ss2 += __shfl_xor_sync(0xFFFFFFFFu, ss2, off);
        s12 += __shfl_xor_sync(0xFFFFFFFFu, s12, off);
    }
    const float inv1 = 1.0f / fmaxf(sqrtf(ss1), EPSN);
    const float inv2 = 1.0f / fmaxf(sqrtf(ss2), EPSN);
    if (lane == 0) g_diag[row] = TEMP_INV * s12 * inv1 * inv2;

    uint2* q1 = (uint2*)(g_a + (size_t)row * D);   // one uint2 = 4 bf16
    uint2* q2 = (uint2*)(g_b + (size_t)row * D);
    #pragma unroll
    for (int i = 0; i < 6; i++) {
        const int idx = lane + i * 32;             // float4 index == uint2 index
        q1[idx] = make_uint2(pack_bf162_u32(v1[i].x * inv1, v1[i].y * inv1),
                             pack_bf162_u32(v1[i].z * inv1, v1[i].w * inv1));
        q2[idx] = make_uint2(pack_bf162_u32(v2[i].x * inv2, v2[i].y * inv2),
                             pack_bf162_u32(v2[i].z * inv2, v2[i].w * inv2));
    }
}

// ---------------------------------------------------------------------------
// Kernel 2: bf16 mma.sync GEMM (proven 72.2us config), 128x128 CTA tile,
// 256 threads, 8 warps (2x4), warp tile 64x32, BK=64, 3-stage cp.async,
// XOR-8 swizzle, f16x2-exp2 fused exp-sum epilogue (shift 4).
// ---------------------------------------------------------------------------
__global__ __launch_bounds__(256)
void k_gemm_fused() {
    extern __shared__ char smem[];
    const uint32_t sbase = smem_u32(smem);
    const int tid = threadIdx.x;
    const int wid = tid >> 5;
    const int lane = tid & 31;
    const int bx = blockIdx.x, by = blockIdx.y;
    const int bi = by * 128, bj = bx * 128;

    const int wy = wid >> 2;
    const int wx = wid & 3;
    const int m0 = wy * 64;
    const int n0 = wx * 32;

    auto load_chunk = [&](int c, int s) {
        const int k0 = c * BK;
        const uint32_t st = sbase + s * STAGE_BYTES;
        #pragma unroll
        for (int i = 0; i < 8; i++) {
            const int idx = tid + i * 256;          // 0..2047
            const int isB = idx >> 10;
            const int id2 = idx & 1023;
            const int row = id2 >> 3;               // 0..127
            const int ch  = id2 & 7;                // 16B chunk in 128B row
            const uint32_t soff = (uint32_t)(row * 128 + ((ch ^ (row & 7)) << 4));
            const __nv_bfloat16* src = (isB ? g_b + (size_t)(bj + row) * D
                                            : g_a + (size_t)(bi + row) * D) + k0 + ch * 8;
            CP_ASYNC16(st + isB * 16384 + soff, src);
        }
        CP_COMMIT();
    };

    uint32_t aRB[4], aR7[4];
    #pragma unroll
    for (int mt = 0; mt < 4; mt++) {
        const int r = m0 + mt * 16 + (lane & 15);
        aRB[mt] = (uint32_t)(r * 128);
        aR7[mt] = (uint32_t)(r & 7);
    }
    uint32_t bRB[2], bR7[2];
    #pragma unroll
    for (int p = 0; p < 2; p++) {
        const int r = n0 + p * 16 + ((lane >> 4) << 3) + (lane & 7);
        bRB[p] = (uint32_t)(r * 128);
        bR7[p] = (uint32_t)(r & 7);
    }
    const uint32_t chA = (uint32_t)(lane >> 4);
    const uint32_t chB = (uint32_t)((lane >> 3) & 1);

    float acc[4][4][4];
    #pragma unroll
    for (int mt = 0; mt < 4; mt++)
        #pragma unroll
        for (int nt = 0; nt < 4; nt++)
            #pragma unroll
            for (int r = 0; r < 4; r++) acc[mt][nt][r] = 0.0f;

    load_chunk(0, 0);
    load_chunk(1, 1);

    for (int c = 0; c < NCH; c++) {
        CP_WAIT(1);
        __syncthreads();
        if (c + 2 < NCH) {
            load_chunk(c + 2, (c + 2) % 3);
        } else {
            CP_COMMIT();
        }

        const uint32_t sA = sbase + (c % 3) * STAGE_BYTES;
        const uint32_t sB = sA + 16384;

        #pragma unroll
        for (int ks = 0; ks < 4; ks++) {
            uint32_t a[4][4];
            #pragma unroll
            for (int mt = 0; mt < 4; mt++) {
                const uint32_t ch = 2 * ks + chA;
                ldmx4(a[mt], sA + aRB[mt] + ((ch ^ aR7[mt]) << 4));
            }
            uint32_t b[4][2];
            #pragma unroll
            for (int p = 0; p < 2; p++) {
                uint32_t t[4];
                const uint32_t ch = 2 * ks + chB;
                ldmx4(t, sB + bRB[p] + ((ch ^ bR7[p]) << 4));
                b[2 * p][0] = t[0]; b[2 * p][1] = t[1];
                b[2 * p + 1][0] = t[2]; b[2 * p + 1][1] = t[3];
            }
            #pragma unroll
            for (int mt = 0; mt < 4; mt++)
                #pragma unroll
                for (int nt = 0; nt < 4; nt++)
                    mma_bf16(acc[mt][nt], a[mt], b[nt]);
        }
    }

    // ---------------- fused epilogue: f16x2 exp2, shift 4 ----------------
    const float S = TEMP_INV * LOG2E;
    const float Bc = -SHIFT * LOG2E;
    const int g = lane >> 2;
    const int tig = lane & 3;

    uint32_t hsum[8];
    #pragma unroll
    for (int h = 0; h < 8; h++) hsum[h] = 0u;

    #pragma unroll
    for (int mt = 0; mt < 4; mt++) {
        #pragma unroll
        for (int nt = 0; nt < 4; nt++) {
            const uint32_t e01 = ex2_f16x2(pack_f16x2(fmaf(acc[mt][nt][0], S, Bc),
                                                      fmaf(acc[mt][nt][1], S, Bc)));
            const uint32_t e23 = ex2_f16x2(pack_f16x2(fmaf(acc[mt][nt][2], S, Bc),
                                                      fmaf(acc[mt][nt][3], S, Bc)));
            hsum[mt * 2 + 0] = hadd2(hsum[mt * 2 + 0], e01);
            hsum[mt * 2 + 1] = hadd2(hsum[mt * 2 + 1], e23);
        }
    }

    float rowsum[8];
    #pragma unroll
    for (int h = 0; h < 8; h++) {
        rowsum[h] = h2_sum_f32(hsum[h]);
        rowsum[h] += __shfl_xor_sync(0xFFFFFFFFu, rowsum[h], 1);
        rowsum[h] += __shfl_xor_sync(0xFFFFFFFFu, rowsum[h], 2);
    }

    __syncthreads();
    float* part = (float*)smem;  // [128][4]
    if (tig == 0) {
        #pragma unroll
        for (int h = 0; h < 8; h++) {
            const int r = m0 + (h >> 1) * 16 + (h & 1) * 8 + g;
            part[r * 4 + wx] = rowsum[h];
        }
    }
    __syncthreads();
    if (tid < 128) {
        const float s = part[tid * 4 + 0] + part[tid * 4 + 1] +
                        part[tid * 4 + 2] + part[tid * 4 + 3];
        g_partial[(size_t)(bi + tid) * 32 + bx] = s;
    }
}

// ---------------------------------------------------------------------------
// Kernel 3: per-row loss + deterministic mean (last block reduces).
// loss_i = log(sum_j exp(l_ij - 4)) + 4 - l_ii(exact)
// ---------------------------------------------------------------------------
__global__ void k_rowloss_fin(float* __restrict__ out) {
    const int row = blockIdx.x * 128 + threadIdx.x;
    const float4* p = (const float4*)(g_partial + (size_t)row * 32);
    float s = 0.0f;
    #pragma unroll
    for (int i = 0; i < 8; i++) {
        float4 v = p[i];
        s += v.x + v.y + v.z + v.w;
    }
    g_rowloss[row] = logf(s) + SHIFT - g_diag[row];

    __threadfence();
    __shared__ bool isLast;
    if (threadIdx.x == 0) {
        isLast = (atomicAdd(&g_done, 1) == 31);
    }
    __syncthreads();
    if (!isLast) return;

    float t = 0.0f;
    const float4* rl = (const float4*)g_rowloss;
    #pragma unroll
    for (int i = 0; i < 8; i++) {
        float4 v = rl[threadIdx.x + i * 128];
        t += v.x + v.y + v.z + v.w;
    }
    __shared__ float sm[128];
    sm[threadIdx.x] = t;
    __syncthreads();
    #pragma unroll
    for (int off = 64; off > 0; off >>= 1) {
        if (threadIdx.x < off) sm[threadIdx.x] += sm[threadIdx.x + off];
        __syncthreads();
    }
    if (threadIdx.x == 0) out[0] = sm[0] / (float)N;
}

// ---------------------------------------------------------------------------
extern "C" void kernel_launch(void* const* d_in, const int* in_sizes, int n_in,
                              void* d_out, int out_size) {
    const float* f1 = (const float*)d_in[0];
    const float* f2 = (const float*)d_in[1];
    float* out = (float*)d_out;

    cudaFuncSetAttribute(k_gemm_fused, cudaFuncAttributeMaxDynamicSharedMemorySize, SMEM_DYN);

    k_norm_cvt<<<N / 8, 256>>>(f1, f2);
    k_gemm_fused<<<dim3(N / 128, N / 128), 256, SMEM_DYN>>>();
    k_rowloss_fin<<<32, 128>>>(out);
}

// round 15
// speedup vs baseline: 1.1544x; 1.0927x over previous
#include <cuda_runtime.h>
#include <cuda_bf16.h>
#include <math.h>
#include <stdint.h>

#define N 4096
#define D 768
#define TEMP_INV 20.0f
#define EPSN 1e-8f
#define SHIFT 4.0f
#define LOG2E 1.44269504089f

#define BK 64
#define NCH (D / BK)          // 12 k-chunks
#define STAGE_BYTES 32768     // 16KB A + 16KB B
#define SMEM_DYN (3 * STAGE_BYTES)   // 96 KB -> 2 CTA/SM

// ---------------------------------------------------------------------------
// Scratch (allocation-free: device globals)
// ---------------------------------------------------------------------------
__device__ __nv_bfloat16 g_a[(size_t)N * D];
__device__ __nv_bfloat16 g_b[(size_t)N * D];
__device__ float g_partial[(size_t)N * 32];
__device__ float g_diag[N];          // exact fp32 diagonal logits
__device__ float g_rowloss[N];
__device__ int   g_done;

// ---------------------------------------------------------------------------
__device__ __forceinline__ uint32_t smem_u32(const void* p) {
    uint32_t a;
    asm("{ .reg .u64 t; cvta.to.shared.u64 t, %1; cvt.u32.u64 %0, t; }" : "=r"(a) : "l"(p));
    return a;
}

#define CP_ASYNC16(dst, src) \
    asm volatile("cp.async.cg.shared.global [%0], [%1], 16;" :: "r"(dst), "l"(src) : "memory")
#define CP_COMMIT() asm volatile("cp.async.commit_group;" ::: "memory")
#define CP_WAIT(n)  asm volatile("cp.async.wait_group %0;" :: "n"(n) : "memory")

__device__ __forceinline__ void ldmx4(uint32_t* r, uint32_t addr) {
    asm volatile("ldmatrix.sync.aligned.m8n8.x4.shared.b16 {%0,%1,%2,%3}, [%4];"
                 : "=r"(r[0]), "=r"(r[1]), "=r"(r[2]), "=r"(r[3]) : "r"(addr));
}

__device__ __forceinline__ void mma_bf16(float* c, const uint32_t* a, const uint32_t* b) {
    asm volatile(
        "mma.sync.aligned.m16n8k16.row.col.f32.bf16.bf16.f32 "
        "{%0,%1,%2,%3}, {%4,%5,%6,%7}, {%8,%9}, {%0,%1,%2,%3};"
        : "+f"(c[0]), "+f"(c[1]), "+f"(c[2]), "+f"(c[3])
        : "r"(a[0]), "r"(a[1]), "r"(a[2]), "r"(a[3]), "r"(b[0]), "r"(b[1]));
}

__device__ __forceinline__ uint32_t pack_f16x2(float x, float y) {
    uint32_t r;
    asm("cvt.rn.f16x2.f32 %0, %1, %2;" : "=r"(r) : "f"(y), "f"(x));
    return r;
}
__device__ __forceinline__ uint32_t ex2_f16x2(uint32_t h) {
    uint32_t r;
    asm("ex2.approx.f16x2 %0, %1;" : "=r"(r) : "r"(h));
    return r;
}
__device__ __forceinline__ uint32_t hadd2(uint32_t a, uint32_t b) {
    uint32_t r;
    asm("add.f16x2 %0, %1, %2;" : "=r"(r) : "r"(a), "r"(b));
    return r;
}
__device__ __forceinline__ float h2_sum_f32(uint32_t h) {
    __half2 v = *reinterpret_cast<__half2*>(&h);
    return __half2float(__low2half(v)) + __half2float(__high2half(v));
}
__device__ __forceinline__ uint32_t pack_bf162_u32(float x, float y) {
    __nv_bfloat162 b = __floats2bfloat162_rn(x, y);
    return *reinterpret_cast<uint32_t*>(&b);
}

// ---------------------------------------------------------------------------
// Kernel 1: warp-per-row L2-normalize BOTH matrices, bf16 out (8B stores),
// exact fp32 diagonal logit. Resets g_done. grid = N/8 = 512 x 256 threads.
// ---------------------------------------------------------------------------
__global__ __launch_bounds__(256)
void k_norm_cvt(const float* __restrict__ f1, const float* __restrict__ f2) {
    if (blockIdx.x == 0 && threadIdx.x == 0) g_done = 0;

    const int wid = threadIdx.x >> 5;
    const int lane = threadIdx.x & 31;
    const int row = blockIdx.x * 8 + wid;

    const float4* p1 = (const float4*)(f1 + (size_t)row * D);
    const float4* p2 = (const float4*)(f2 + (size_t)row * D);
    float4 v1[6], v2[6];
    float ss1 = 0.0f, ss2 = 0.0f, s12 = 0.0f;
    #pragma unroll
    for (int i = 0; i < 6; i++) {
        v1[i] = p1[lane + i * 32];
        v2[i] = p2[lane + i * 32];
        ss1 += v1[i].x * v1[i].x + v1[i].y * v1[i].y + v1[i].z * v1[i].z + v1[i].w * v1[i].w;
        ss2 += v2[i].x * v2[i].x + v2[i].y * v2[i].y + v2[i].z * v2[i].z + v2[i].w * v2[i].w;
        s12 += v1[i].x * v2[i].x + v1[i].y * v2[i].y + v1[i].z * v2[i].z + v1[i].w * v2[i].w;
    }
    #pragma unroll
    for (int off = 16; off > 0; off >>= 1) {
        ss1 += __shfl_xor_sync(0xFFFFFFFFu, ss1, off);
        ss2 += __shfl_xor_sync(0xFFFFFFFFu, ss2, off);
        s12 += __shfl_xor_sync(0xFFFFFFFFu, s12, off);
    }
    const float inv1 = 1.0f / fmaxf(sqrtf(ss1), EPSN);
    const float inv2 = 1.0f / fmaxf(sqrtf(ss2), EPSN);
    if (lane == 0) g_diag[row] = TEMP_INV * s12 * inv1 * inv2;

    uint2* q1 = (uint2*)(g_a + (size_t)row * D);   // one uint2 = 4 bf16
    uint2* q2 = (uint2*)(g_b + (size_t)row * D);
    #pragma unroll
    for (int i = 0; i < 6; i++) {
        const int idx = lane + i * 32;             // float4 index == uint2 index
        q1[idx] = make_uint2(pack_bf162_u32(v1[i].x * inv1, v1[i].y * inv1),
                             pack_bf162_u32(v1[i].z * inv1, v1[i].w * inv1));
        q2[idx] = make_uint2(pack_bf162_u32(v2[i].x * inv2, v2[i].y * inv2),
                             pack_bf162_u32(v2[i].z * inv2, v2[i].w * inv2));
    }
}

// ---------------------------------------------------------------------------
// Kernel 2: bf16 mma.sync GEMM (proven 72.2us config), 128x128 CTA tile,
// 256 threads, 8 warps (2x4), warp tile 64x32, BK=64, 3-stage cp.async,
// XOR-8 swizzle, fully unrolled chunk loop (const stage indices),
// f16x2-exp2 fused exp-sum epilogue (shift 4).
// ---------------------------------------------------------------------------
__global__ __launch_bounds__(256)
void k_gemm_fused() {
    extern __shared__ char smem[];
    const uint32_t sbase = smem_u32(smem);
    const int tid = threadIdx.x;
    const int wid = tid >> 5;
    const int lane = tid & 31;
    const int bx = blockIdx.x, by = blockIdx.y;
    const int bi = by * 128, bj = bx * 128;

    const int wy = wid >> 2;
    const int wx = wid & 3;
    const int m0 = wy * 64;
    const int n0 = wx * 32;

    auto load_chunk = [&](int c, int s) {
        const int k0 = c * BK;
        const uint32_t st = sbase + s * STAGE_BYTES;
        #pragma unroll
        for (int i = 0; i < 8; i++) {
            const int idx = tid + i * 256;          // 0..2047
            const int isB = idx >> 10;
            const int id2 = idx & 1023;
            const int row = id2 >> 3;               // 0..127
            const int ch  = id2 & 7;                // 16B chunk in 128B row
            const uint32_t soff = (uint32_t)(row * 128 + ((ch ^ (row & 7)) << 4));
            const __nv_bfloat16* src = (isB ? g_b + (size_t)(bj + row) * D
                                            : g_a + (size_t)(bi + row) * D) + k0 + ch * 8;
            CP_ASYNC16(st + isB * 16384 + soff, src);
        }
        CP_COMMIT();
    };

    uint32_t aRB[4], aR7[4];
    #pragma unroll
    for (int mt = 0; mt < 4; mt++) {
        const int r = m0 + mt * 16 + (lane & 15);
        aRB[mt] = (uint32_t)(r * 128);
        aR7[mt] = (uint32_t)(r & 7);
    }
    uint32_t bRB[2], bR7[2];
    #pragma unroll
    for (int p = 0; p < 2; p++) {
        const int r = n0 + p * 16 + ((lane >> 4) << 3) + (lane & 7);
        bRB[p] = (uint32_t)(r * 128);
        bR7[p] = (uint32_t)(r & 7);
    }
    const uint32_t chA = (uint32_t)(lane >> 4);
    const uint32_t chB = (uint32_t)((lane >> 3) & 1);

    float acc[4][4][4];
    #pragma unroll
    for (int mt = 0; mt < 4; mt++)
        #pragma unroll
        for (int nt = 0; nt < 4; nt++)
            #pragma unroll
            for (int r = 0; r < 4; r++) acc[mt][nt][r] = 0.0f;

    load_chunk(0, 0);
    load_chunk(1, 1);

    #pragma unroll
    for (int c = 0; c < NCH; c++) {
        CP_WAIT(1);
        __syncthreads();
        if (c + 2 < NCH) {
            load_chunk(c + 2, (c + 2) % 3);
        } else {
            CP_COMMIT();
        }

        const uint32_t sA = sbase + (c % 3) * STAGE_BYTES;
        const uint32_t sB = sA + 16384;

        #pragma unroll
        for (int ks = 0; ks < 4; ks++) {
            uint32_t a[4][4];
            #pragma unroll
            for (int mt = 0; mt < 4; mt++) {
                const uint32_t ch = 2 * ks + chA;
                ldmx4(a[mt], sA + aRB[mt] + ((ch ^ aR7[mt]) << 4));
            }
            uint32_t b[4][2];
            #pragma unroll
            for (int p = 0; p < 2; p++) {
                uint32_t t[4];
                const uint32_t ch = 2 * ks + chB;
                ldmx4(t, sB + bRB[p] + ((ch ^ bR7[p]) << 4));
                b[2 * p][0] = t[0]; b[2 * p][1] = t[1];
                b[2 * p + 1][0] = t[2]; b[2 * p + 1][1] = t[3];
            }
            #pragma unroll
            for (int mt = 0; mt < 4; mt++)
                #pragma unroll
                for (int nt = 0; nt < 4; nt++)
                    mma_bf16(acc[mt][nt], a[mt], b[nt]);
        }
    }

    // ---------------- fused epilogue: f16x2 exp2, shift 4 ----------------
    const float S = TEMP_INV * LOG2E;
    const float Bc = -SHIFT * LOG2E;
    const int g = lane >> 2;
    const int tig = lane & 3;

    uint32_t hsum[8];
    #pragma unroll
    for (int h = 0; h < 8; h++) hsum[h] = 0u;

    #pragma unroll
    for (int mt = 0; mt < 4; mt++) {
        #pragma unroll
        for (int nt = 0; nt < 4; nt++) {
            const uint32_t e01 = ex2_f16x2(pack_f16x2(fmaf(acc[mt][nt][0], S, Bc),
                                                      fmaf(acc[mt][nt][1], S, Bc)));
            const uint32_t e23 = ex2_f16x2(pack_f16x2(fmaf(acc[mt][nt][2], S, Bc),
                                                      fmaf(acc[mt][nt][3], S, Bc)));
            hsum[mt * 2 + 0] = hadd2(hsum[mt * 2 + 0], e01);
            hsum[mt * 2 + 1] = hadd2(hsum[mt * 2 + 1], e23);
        }
    }

    float rowsum[8];
    #pragma unroll
    for (int h = 0; h < 8; h++) {
        rowsum[h] = h2_sum_f32(hsum[h]);
        rowsum[h] += __shfl_xor_sync(0xFFFFFFFFu, rowsum[h], 1);
        rowsum[h] += __shfl_xor_sync(0xFFFFFFFFu, rowsum[h], 2);
    }

    __syncthreads();
    float* part = (float*)smem;  // [128][4]
    if (tig == 0) {
        #pragma unroll
        for (int h = 0; h < 8; h++) {
            const int r = m0 + (h >> 1) * 16 + (h & 1) * 8 + g;
            part[r * 4 + wx] = rowsum[h];
        }
    }
    __syncthreads();
    if (tid < 128) {
        const float s = part[tid * 4 + 0] + part[tid * 4 + 1] +
                        part[tid * 4 + 2] + part[tid * 4 + 3];
        g_partial[(size_t)(bi + tid) * 32 + bx] = s;
    }
}

// ---------------------------------------------------------------------------
// Kernel 3: per-row loss + deterministic mean (last block reduces).
// loss_i = log(sum_j exp(l_ij - 4)) + 4 - l_ii(exact)
// ---------------------------------------------------------------------------
__global__ void k_rowloss_fin(float* __restrict__ out) {
    const int row = blockIdx.x * 128 + threadIdx.x;
    const float4* p = (const float4*)(g_partial + (size_t)row * 32);
    float s = 0.0f;
    #pragma unroll
    for (int i = 0; i < 8; i++) {
        float4 v = p[i];
        s += v.x + v.y + v.z + v.w;
    }
    g_rowloss[row] = logf(s) + SHIFT - g_diag[row];

    __threadfence();
    __shared__ bool isLast;
    if (threadIdx.x == 0) {
        isLast = (atomicAdd(&g_done, 1) == 31);
    }
    __syncthreads();
    if (!isLast) return;

    float t = 0.0f;
    const float4* rl = (const float4*)g_rowloss;
    #pragma unroll
    for (int i = 0; i < 8; i++) {
        float4 v = rl[threadIdx.x + i * 128];
        t += v.x + v.y + v.z + v.w;
    }
    __shared__ float sm[128];
    sm[threadIdx.x] = t;
    __syncthreads();
    #pragma unroll
    for (int off = 64; off > 0; off >>= 1) {
        if (threadIdx.x < off) sm[threadIdx.x] += sm[threadIdx.x + off];
        __syncthreads();
    }
    if (threadIdx.x == 0) out[0] = sm[0] / (float)N;
}

// ---------------------------------------------------------------------------
extern "C" void kernel_launch(void* const* d_in, const int* in_sizes, int n_in,
                              void* d_out, int out_size) {
    const float* f1 = (const float*)d_in[0];
    const float* f2 = (const float*)d_in[1];
    float* out = (float*)d_out;

    cudaFuncSetAttribute(k_gemm_fused, cudaFuncAttributeMaxDynamicSharedMemorySize, SMEM_DYN);

    k_norm_cvt<<<N / 8, 256>>>(f1, f2);
    k_gemm_fused<<<dim3(N / 128, N / 128), 256, SMEM_DYN>>>();
    k_rowloss_fin<<<32, 128>>>(out);
}

// round 16
// speedup vs baseline: 1.1942x; 1.0344x over previous
#include <cuda_runtime.h>
#include <cuda_bf16.h>
#include <math.h>
#include <stdint.h>

#define N 4096
#define D 768
#define TEMP_INV 20.0f
#define EPSN 1e-8f
#define SHIFT 4.0f
#define LOG2E 1.44269504089f

#define BK 64
#define NCH (D / BK)          // 12 k-chunks
#define STAGE_BYTES 32768     // 16KB A + 16KB B
#define SMEM_DYN (3 * STAGE_BYTES)   // 96 KB -> 2 CTA/SM

// ---------------------------------------------------------------------------
// Scratch (allocation-free: device globals)
// ---------------------------------------------------------------------------
__device__ __nv_bfloat16 g_a[(size_t)N * D];
__device__ __nv_bfloat16 g_b[(size_t)N * D];
__device__ float g_partial[(size_t)N * 32];
__device__ float g_diag[N];          // exact fp32 diagonal logits
__device__ float g_rowloss[N];
__device__ int   g_done;

// ---------------------------------------------------------------------------
__device__ __forceinline__ uint32_t smem_u32(const void* p) {
    uint32_t a;
    asm("{ .reg .u64 t; cvta.to.shared.u64 t, %1; cvt.u32.u64 %0, t; }" : "=r"(a) : "l"(p));
    return a;
}

#define CP_ASYNC16(dst, src) \
    asm volatile("cp.async.cg.shared.global [%0], [%1], 16;" :: "r"(dst), "l"(src) : "memory")
#define CP_COMMIT() asm volatile("cp.async.commit_group;" ::: "memory")
#define CP_WAIT(n)  asm volatile("cp.async.wait_group %0;" :: "n"(n) : "memory")

__device__ __forceinline__ void ldmx4(uint32_t* r, uint32_t addr) {
    asm volatile("ldmatrix.sync.aligned.m8n8.x4.shared.b16 {%0,%1,%2,%3}, [%4];"
                 : "=r"(r[0]), "=r"(r[1]), "=r"(r[2]), "=r"(r[3]) : "r"(addr));
}

__device__ __forceinline__ void mma_bf16(float* c, const uint32_t* a, const uint32_t* b) {
    asm volatile(
        "mma.sync.aligned.m16n8k16.row.col.f32.bf16.bf16.f32 "
        "{%0,%1,%2,%3}, {%4,%5,%6,%7}, {%8,%9}, {%0,%1,%2,%3};"
        : "+f"(c[0]), "+f"(c[1]), "+f"(c[2]), "+f"(c[3])
        : "r"(a[0]), "r"(a[1]), "r"(a[2]), "r"(a[3]), "r"(b[0]), "r"(b[1]));
}

__device__ __forceinline__ uint32_t pack_f16x2(float x, float y) {
    uint32_t r;
    asm("cvt.rn.f16x2.f32 %0, %1, %2;" : "=r"(r) : "f"(y), "f"(x));
    return r;
}
__device__ __forceinline__ uint32_t ex2_f16x2(uint32_t h) {
    uint32_t r;
    asm("ex2.approx.f16x2 %0, %1;" : "=r"(r) : "r"(h));
    return r;
}
__device__ __forceinline__ uint32_t hadd2(uint32_t a, uint32_t b) {
    uint32_t r;
    asm("add.f16x2 %0, %1, %2;" : "=r"(r) : "r"(a), "r"(b));
    return r;
}
__device__ __forceinline__ float h2_sum_f32(uint32_t h) {
    __half2 v = *reinterpret_cast<__half2*>(&h);
    return __half2float(__low2half(v)) + __half2float(__high2half(v));
}
__device__ __forceinline__ uint32_t pack_bf162_u32(float x, float y) {
    __nv_bfloat162 b = __floats2bfloat162_rn(x, y);
    return *reinterpret_cast<uint32_t*>(&b);
}

// ---------------------------------------------------------------------------
// Kernel 1: warp-per-row L2-normalize BOTH matrices, bf16 out (8B stores),
// exact fp32 diagonal logit. Resets g_done. grid = N/8 = 512 x 256 threads.
// ---------------------------------------------------------------------------
__global__ __launch_bounds__(256)
void k_norm_cvt(const float* __restrict__ f1, const float* __restrict__ f2) {
    if (blockIdx.x == 0 && threadIdx.x == 0) g_done = 0;

    const int wid = threadIdx.x >> 5;
    const int lane = threadIdx.x & 31;
    const int row = blockIdx.x * 8 + wid;

    const float4* p1 = (const float4*)(f1 + (size_t)row * D);
    const float4* p2 = (const float4*)(f2 + (size_t)row * D);
    float4 v1[6], v2[6];
    float ss1 = 0.0f, ss2 = 0.0f, s12 = 0.0f;
    #pragma unroll
    for (int i = 0; i < 6; i++) {
        v1[i] = p1[lane + i * 32];
        v2[i] = p2[lane + i * 32];
        ss1 += v1[i].x * v1[i].x + v1[i].y * v1[i].y + v1[i].z * v1[i].z + v1[i].w * v1[i].w;
        ss2 += v2[i].x * v2[i].x + v2[i].y * v2[i].y + v2[i].z * v2[i].z + v2[i].w * v2[i].w;
        s12 += v1[i].x * v2[i].x + v1[i].y * v2[i].y + v1[i].z * v2[i].z + v1[i].w * v2[i].w;
    }
    #pragma unroll
    for (int off = 16; off > 0; off >>= 1) {
        ss1 += __shfl_xor_sync(0xFFFFFFFFu, ss1, off);
        ss2 += __shfl_xor_sync(0xFFFFFFFFu, ss2, off);
        s12 += __shfl_xor_sync(0xFFFFFFFFu, s12, off);
    }
    const float inv1 = 1.0f / fmaxf(sqrtf(ss1), EPSN);
    const float inv2 = 1.0f / fmaxf(sqrtf(ss2), EPSN);
    if (lane == 0) g_diag[row] = TEMP_INV * s12 * inv1 * inv2;

    uint2* q1 = (uint2*)(g_a + (size_t)row * D);   // one uint2 = 4 bf16
    uint2* q2 = (uint2*)(g_b + (size_t)row * D);
    #pragma unroll
    for (int i = 0; i < 6; i++) {
        const int idx = lane + i * 32;             // float4 index == uint2 index
        q1[idx] = make_uint2(pack_bf162_u32(v1[i].x * inv1, v1[i].y * inv1),
                             pack_bf162_u32(v1[i].z * inv1, v1[i].w * inv1));
        q2[idx] = make_uint2(pack_bf162_u32(v2[i].x * inv2, v2[i].y * inv2),
                             pack_bf162_u32(v2[i].z * inv2, v2[i].w * inv2));
    }
}

// ---------------------------------------------------------------------------
// Kernel 2: bf16 mma.sync GEMM, 128x128 CTA tile, 256 threads, 8 warps (2x4),
// warp tile 64x32, BK=64, 3-stage cp.async, XOR-8 swizzle, FULLY UNROLLED
// chunk loop (66.3us proven) with prefetch issues SPREAD across ks-batches
// to avoid the chunk-head LSU burst. f16x2-exp2 fused epilogue (shift 4).
// ---------------------------------------------------------------------------
__global__ __launch_bounds__(256)
void k_gemm_fused() {
    extern __shared__ char smem[];
    const uint32_t sbase = smem_u32(smem);
    const int tid = threadIdx.x;
    const int wid = tid >> 5;
    const int lane = tid & 31;
    const int bx = blockIdx.x, by = blockIdx.y;
    const int bi = by * 128, bj = bx * 128;

    const int wy = wid >> 2;
    const int wx = wid & 3;
    const int m0 = wy * 64;
    const int n0 = wx * 32;

    // issue a PAIR of cp.asyncs (part pp of 4) for chunk c into stage s
    auto load_part = [&](int c, int s, int pp) {
        const int k0 = c * BK;
        const uint32_t st = sbase + s * STAGE_BYTES;
        #pragma unroll
        for (int i = pp * 2; i < pp * 2 + 2; i++) {
            const int idx = tid + i * 256;          // 0..2047
            const int isB = idx >> 10;
            const int id2 = idx & 1023;
            const int row = id2 >> 3;               // 0..127
            const int ch  = id2 & 7;                // 16B chunk in 128B row
            const uint32_t soff = (uint32_t)(row * 128 + ((ch ^ (row & 7)) << 4));
            const __nv_bfloat16* src = (isB ? g_b + (size_t)(bj + row) * D
                                            : g_a + (size_t)(bi + row) * D) + k0 + ch * 8;
            CP_ASYNC16(st + isB * 16384 + soff, src);
        }
    };
    auto load_chunk = [&](int c, int s) {
        #pragma unroll
        for (int pp = 0; pp < 4; pp++) load_part(c, s, pp);
        CP_COMMIT();
    };

    uint32_t aRB[4], aR7[4];
    #pragma unroll
    for (int mt = 0; mt < 4; mt++) {
        const int r = m0 + mt * 16 + (lane & 15);
        aRB[mt] = (uint32_t)(r * 128);
        aR7[mt] = (uint32_t)(r & 7);
    }
    uint32_t bRB[2], bR7[2];
    #pragma unroll
    for (int p = 0; p < 2; p++) {
        const int r = n0 + p * 16 + ((lane >> 4) << 3) + (lane & 7);
        bRB[p] = (uint32_t)(r * 128);
        bR7[p] = (uint32_t)(r & 7);
    }
    const uint32_t chA = (uint32_t)(lane >> 4);
    const uint32_t chB = (uint32_t)((lane >> 3) & 1);

    float acc[4][4][4];
    #pragma unroll
    for (int mt = 0; mt < 4; mt++)
        #pragma unroll
        for (int nt = 0; nt < 4; nt++)
            #pragma unroll
            for (int r = 0; r < 4; r++) acc[mt][nt][r] = 0.0f;

    load_chunk(0, 0);
    load_chunk(1, 1);

    #pragma unroll
    for (int c = 0; c < NCH; c++) {
        CP_WAIT(1);
        __syncthreads();

        const uint32_t sA = sbase + (c % 3) * STAGE_BYTES;
        const uint32_t sB = sA + 16384;
        const bool doPrefetch = (c + 2 < NCH);

        #pragma unroll
        for (int ks = 0; ks < 4; ks++) {
            uint32_t a[4][4];
            #pragma unroll
            for (int mt = 0; mt < 4; mt++) {
                const uint32_t ch = 2 * ks + chA;
                ldmx4(a[mt], sA + aRB[mt] + ((ch ^ aR7[mt]) << 4));
            }
            uint32_t b[4][2];
            #pragma unroll
            for (int p = 0; p < 2; p++) {
                uint32_t t[4];
                const uint32_t ch = 2 * ks + chB;
                ldmx4(t, sB + bRB[p] + ((ch ^ bR7[p]) << 4));
                b[2 * p][0] = t[0]; b[2 * p][1] = t[1];
                b[2 * p + 1][0] = t[2]; b[2 * p + 1][1] = t[3];
            }
            // spread prefetch: 2 cp.asyncs per ks batch instead of 8 up front
            if (doPrefetch) load_part(c + 2, (c + 2) % 3, ks);
            #pragma unroll
            for (int mt = 0; mt < 4; mt++)
                #pragma unroll
                for (int nt = 0; nt < 4; nt++)
                    mma_bf16(acc[mt][nt], a[mt], b[nt]);
        }
        CP_COMMIT();   // close this chunk's prefetch group (empty on last 2)
    }

    // ---------------- fused epilogue: f16x2 exp2, shift 4 ----------------
    const float S = TEMP_INV * LOG2E;
    const float Bc = -SHIFT * LOG2E;
    const int g = lane >> 2;
    const int tig = lane & 3;

    uint32_t hsum[8];
    #pragma unroll
    for (int h = 0; h < 8; h++) hsum[h] = 0u;

    #pragma unroll
    for (int mt = 0; mt < 4; mt++) {
        #pragma unroll
        for (int nt = 0; nt < 4; nt++) {
            const uint32_t e01 = ex2_f16x2(pack_f16x2(fmaf(acc[mt][nt][0], S, Bc),
                                                      fmaf(acc[mt][nt][1], S, Bc)));
            const uint32_t e23 = ex2_f16x2(pack_f16x2(fmaf(acc[mt][nt][2], S, Bc),
                                                      fmaf(acc[mt][nt][3], S, Bc)));
            hsum[mt * 2 + 0] = hadd2(hsum[mt * 2 + 0], e01);
            hsum[mt * 2 + 1] = hadd2(hsum[mt * 2 + 1], e23);
        }
    }

    float rowsum[8];
    #pragma unroll
    for (int h = 0; h < 8; h++) {
        rowsum[h] = h2_sum_f32(hsum[h]);
        rowsum[h] += __shfl_xor_sync(0xFFFFFFFFu, rowsum[h], 1);
        rowsum[h] += __shfl_xor_sync(0xFFFFFFFFu, rowsum[h], 2);
    }

    __syncthreads();
    float* part = (float*)smem;  // [128][4]
    if (tig == 0) {
        #pragma unroll
        for (int h = 0; h < 8; h++) {
            const int r = m0 + (h >> 1) * 16 + (h & 1) * 8 + g;
            part[r * 4 + wx] = rowsum[h];
        }
    }
    __syncthreads();
    if (tid < 128) {
        const float s = part[tid * 4 + 0] + part[tid * 4 + 1] +
                        part[tid * 4 + 2] + part[tid * 4 + 3];
        g_partial[(size_t)(bi + tid) * 32 + bx] = s;
    }
}

// ---------------------------------------------------------------------------
// Kernel 3: per-row loss + deterministic mean (last block reduces).
// loss_i = log(sum_j exp(l_ij - 4)) + 4 - l_ii(exact)
// ---------------------------------------------------------------------------
__global__ void k_rowloss_fin(float* __restrict__ out) {
    const int row = blockIdx.x * 128 + threadIdx.x;
    const float4* p = (const float4*)(g_partial + (size_t)row * 32);
    float s = 0.0f;
    #pragma unroll
    for (int i = 0; i < 8; i++) {
        float4 v = p[i];
        s += v.x + v.y + v.z + v.w;
    }
    g_rowloss[row] = logf(s) + SHIFT - g_diag[row];

    __threadfence();
    __shared__ bool isLast;
    if (threadIdx.x == 0) {
        isLast = (atomicAdd(&g_done, 1) == 31);
    }
    __syncthreads();
    if (!isLast) return;

    float t = 0.0f;
    const float4* rl = (const float4*)g_rowloss;
    #pragma unroll
    for (int i = 0; i < 8; i++) {
        float4 v = rl[threadIdx.x + i * 128];
        t += v.x + v.y + v.z + v.w;
    }
    __shared__ float sm[128];
    sm[threadIdx.x] = t;
    __syncthreads();
    #pragma unroll
    for (int off = 64; off > 0; off >>= 1) {
        if (threadIdx.x < off) sm[threadIdx.x] += sm[threadIdx.x + off];
        __syncthreads();
    }
    if (threadIdx.x == 0) out[0] = sm[0] / (float)N;
}

// ---------------------------------------------------------------------------
extern "C" void kernel_launch(void* const* d_in, const int* in_sizes, int n_in,
                              void* d_out, int out_size) {
    const float* f1 = (const float*)d_in[0];
    const float* f2 = (const float*)d_in[1];
    float* out = (float*)d_out;

    cudaFuncSetAttribute(k_gemm_fused, cudaFuncAttributeMaxDynamicSharedMemorySize, SMEM_DYN);

    k_norm_cvt<<<N / 8, 256>>>(f1, f2);
    k_gemm_fused<<<dim3(N / 128, N / 128), 256, SMEM_DYN>>>();
    k_rowloss_fin<<<32, 128>>>(out);
}